// round 13
// baseline (speedup 1.0000x reference)
#include <cuda_runtime.h>
#include <math.h>

#define BATCH 64
#define DMODEL 4096
#define NHEADS 32
#define KVHEADS 8
#define HDIM 128
#define NMAT 48              // 32 q mats + 8 k mats + 8 v mats, each D x H
#define KSPLIT 8
#define KCHUNK (DMODEL / KSPLIT)   // 512
#define CACHE_HALF 67108864L       // 65536 * 8 * 128
#define ATTN_OUT_OFF 134217728L    // 2 * CACHE_HALF

// ---------------- scratch (allocation-free, __device__ globals) ----------------
__device__ __align__(16) float g_qkv_part[NMAT * KSPLIT * BATCH * HDIM]; // 12.6 MB
__device__ __align__(16) float g_qbuf[BATCH * NHEADS * HDIM];
__device__ __align__(16) float g_kbuf[BATCH * KVHEADS * HDIM];
__device__ __align__(16) float g_vbuf[BATCH * KVHEADS * HDIM];
__device__ __align__(16) float g_obuf[BATCH * NHEADS * HDIM];
__device__ __align__(16) float g_opart[4 * BATCH * DMODEL];              // 4 MB

// ---------------- Kernel 1: QKV projection (48 DxH mats, K-split 8) ----------------
// grid = 48*8 blocks, 256 threads. Block computes 64(b) x 128(h) partial over 512 K.
__global__ __launch_bounds__(256) void qkv_gemm(
    const float* __restrict__ x,      // (64, 4096)
    const float* __restrict__ q_w,    // (32, 4096, 128)
    const float* __restrict__ kv_w)   // (2, 8, 4096, 128) -> 16 mats
{
    int mat = blockIdx.x >> 3;
    int ks  = blockIdx.x & 7;
    const float* W = (mat < 32) ? (q_w  + (size_t)mat * DMODEL * HDIM)
                                : (kv_w + (size_t)(mat - 32) * DMODEL * HDIM);
    int d0 = ks * KCHUNK;

    __shared__ float xs[64][36];    // 64 b x 32 k, pad 36 (16B-aligned rows)
    __shared__ float ws[32][132];   // 32 k x 128 h, pad 132

    int t  = threadIdx.x;
    int ty = t >> 4;   // 0..15 -> m tile
    int tx = t & 15;   // 0..15 -> h tile

    float acc[4][8];
#pragma unroll
    for (int i = 0; i < 4; i++)
#pragma unroll
        for (int j = 0; j < 8; j++) acc[i][j] = 0.f;

    for (int dt = 0; dt < KCHUNK; dt += 32) {
        // load x tile: 64 rows x 32 floats = 512 float4
#pragma unroll
        for (int r = 0; r < 2; r++) {
            int f = t + 256 * r;
            int row = f >> 3, q4 = f & 7;
            float4 v = *(const float4*)(x + (size_t)row * DMODEL + d0 + dt + q4 * 4);
            *(float4*)&xs[row][q4 * 4] = v;
        }
        // load W tile: 32 rows x 128 floats = 1024 float4
#pragma unroll
        for (int r = 0; r < 4; r++) {
            int f = t + 256 * r;
            int row = f >> 5, q4 = f & 31;
            float4 v = *(const float4*)(W + (size_t)(d0 + dt + row) * HDIM + q4 * 4);
            *(float4*)&ws[row][q4 * 4] = v;
        }
        __syncthreads();
#pragma unroll
        for (int kk = 0; kk < 32; kk++) {
            float a0 = xs[ty * 4 + 0][kk];
            float a1 = xs[ty * 4 + 1][kk];
            float a2 = xs[ty * 4 + 2][kk];
            float a3 = xs[ty * 4 + 3][kk];
            float4 b0 = *(const float4*)&ws[kk][tx * 8];
            float4 b1 = *(const float4*)&ws[kk][tx * 8 + 4];
            acc[0][0] += a0 * b0.x; acc[0][1] += a0 * b0.y; acc[0][2] += a0 * b0.z; acc[0][3] += a0 * b0.w;
            acc[0][4] += a0 * b1.x; acc[0][5] += a0 * b1.y; acc[0][6] += a0 * b1.z; acc[0][7] += a0 * b1.w;
            acc[1][0] += a1 * b0.x; acc[1][1] += a1 * b0.y; acc[1][2] += a1 * b0.z; acc[1][3] += a1 * b0.w;
            acc[1][4] += a1 * b1.x; acc[1][5] += a1 * b1.y; acc[1][6] += a1 * b1.z; acc[1][7] += a1 * b1.w;
            acc[2][0] += a2 * b0.x; acc[2][1] += a2 * b0.y; acc[2][2] += a2 * b0.z; acc[2][3] += a2 * b0.w;
            acc[2][4] += a2 * b1.x; acc[2][5] += a2 * b1.y; acc[2][6] += a2 * b1.z; acc[2][7] += a2 * b1.w;
            acc[3][0] += a3 * b0.x; acc[3][1] += a3 * b0.y; acc[3][2] += a3 * b0.z; acc[3][3] += a3 * b0.w;
            acc[3][4] += a3 * b1.x; acc[3][5] += a3 * b1.y; acc[3][6] += a3 * b1.z; acc[3][7] += a3 * b1.w;
        }
        __syncthreads();
    }

    float* dst = g_qkv_part + ((size_t)(mat * 8 + ks) * 64) * 128;
#pragma unroll
    for (int i = 0; i < 4; i++) {
        int row = ty * 4 + i;
        *(float4*)&dst[row * 128 + tx * 8]     = make_float4(acc[i][0], acc[i][1], acc[i][2], acc[i][3]);
        *(float4*)&dst[row * 128 + tx * 8 + 4] = make_float4(acc[i][4], acc[i][5], acc[i][6], acc[i][7]);
    }
}

// ---------------- Kernel 2: reduce K-split partials + RoPE ----------------
// one thread per (mat, b, j) with j < 64 (rotation pair j, j+64)
__global__ __launch_bounds__(256) void reduce_rope(const int* __restrict__ context_lens)
{
    int tid = blockIdx.x * 256 + threadIdx.x;
    if (tid >= NMAT * BATCH * 64) return;
    int mat = tid >> 12;
    int rem = tid & 4095;
    int b = rem >> 6;
    int j = rem & 63;

    float v1 = 0.f, v2 = 0.f;
    size_t off = ((size_t)(mat * 8) * 64 + b) * 128;
#pragma unroll
    for (int ks = 0; ks < 8; ks++) {
        v1 += g_qkv_part[off + j];
        v2 += g_qkv_part[off + 64 + j];
        off += 64 * 128;
    }

    float o1 = v1, o2 = v2;
    if (mat < 40) {  // rope on q (0..31) and k (32..39), not v
        float pos = (float)(context_lens[b] - 1);
        float ts = powf(10000.0f, (float)j * (1.0f / 64.0f));
        float ang = pos / ts;
        float s = sinf(ang), c = cosf(ang);
        o1 = v1 * c - v2 * s;
        o2 = v2 * c + v1 * s;
    }

    if (mat < 32) {
        float* d = g_qbuf + ((size_t)b * 32 + mat) * 128;
        d[j] = o1; d[j + 64] = o2;
    } else if (mat < 40) {
        float* d = g_kbuf + ((size_t)b * 8 + (mat - 32)) * 128;
        d[j] = o1; d[j + 64] = o2;
    } else {
        float* d = g_vbuf + ((size_t)b * 8 + (mat - 40)) * 128;
        d[j] = o1; d[j + 64] = o2;
    }
}

// ---------------- Kernel 3: scatter new k/v rows into the output cache ----------------
__global__ void cache_scatter(const int* __restrict__ slot_mapping, float* __restrict__ out)
{
    int b = blockIdx.x;
    int slot = slot_mapping[b];
    int t = threadIdx.x;  // 256 threads, 256 float4 per (k,v) row group of 1024 floats
    const float4* ksrc = (const float4*)(g_kbuf + (size_t)b * 1024);
    const float4* vsrc = (const float4*)(g_vbuf + (size_t)b * 1024);
    float4* dk = (float4*)(out + (size_t)slot * 1024);
    float4* dv = (float4*)(out + CACHE_HALF + (size_t)slot * 1024);
    dk[t] = ksrc[t];
    dv[t] = vsrc[t];
}

// ---------------- Kernel 4: paged attention (online softmax, chunk=32) ----------------
// grid = 64*8 blocks (b, kv-head), 256 threads, G=4 query heads per block.
__global__ __launch_bounds__(256) void attn_kernel(
    const float* __restrict__ cache,        // (2, 65536, 8, 128) ORIGINAL
    const int*   __restrict__ block_tables, // (64, 64)
    const int*   __restrict__ context_lens) // (64,)
{
    int b   = blockIdx.x >> 3;
    int kvh = blockIdx.x & 7;
    int t = threadIdx.x;

    __shared__ float q_s[4][132];
    __shared__ float k_s[32][132];
    __shared__ float v_s[32][132];
    __shared__ float logit_s[4][32];
    __shared__ float prob_s[4][32];
    __shared__ float m_sh[4], newm_sh[4], corr_sh[4];
    __shared__ int   bt_s[64];

    int ctx = context_lens[b];
    if (t < 64) bt_s[t] = block_tables[b * 64 + t];

    const float sm_scale = 0.08838834764831845f;  // 128^-0.5
#pragma unroll
    for (int r = 0; r < 2; r++) {
        int f = t + 256 * r;
        int g = f >> 7, h = f & 127;
        q_s[g][h] = g_qbuf[((size_t)b * 32 + kvh * 4 + g) * 128 + h] * sm_scale;
    }
    if (t < 4) m_sh[t] = -INFINITY;

    float acc0 = 0.f, acc1 = 0.f, lsum = 0.f;
    int g2 = t >> 6;    // 0..3 accumulation head
    int hh = t & 63;    // output pair index
    __syncthreads();

    const float* kc = cache;
    const float* vc = cache + CACHE_HALF;

    int nchunk = (ctx + 31) >> 5;
    for (int c = 0; c < nchunk; c++) {
        int p0 = c << 5;
        // load K/V chunk: 32 pos x 128 floats each = 1024 float4 per tensor
#pragma unroll
        for (int r = 0; r < 4; r++) {
            int f = t + 256 * r;
            int row = f >> 5;        // 0..31
            int q4  = f & 31;
            int pos = p0 + row;
            float4 kval = make_float4(0.f, 0.f, 0.f, 0.f);
            float4 vval = kval;
            if (pos < ctx) {
                if (pos == ctx - 1) {
                    kval = *(const float4*)(g_kbuf + ((size_t)b * 8 + kvh) * 128 + q4 * 4);
                    vval = *(const float4*)(g_vbuf + ((size_t)b * 8 + kvh) * 128 + q4 * 4);
                } else {
                    int slot = bt_s[pos >> 4] * 16 + (pos & 15);
                    size_t off = (size_t)slot * 1024 + kvh * 128 + q4 * 4;
                    kval = *(const float4*)(kc + off);
                    vval = *(const float4*)(vc + off);
                }
            }
            *(float4*)&k_s[row][q4 * 4] = kval;
            *(float4*)&v_s[row][q4 * 4] = vval;
        }
        __syncthreads();

        // phase 1: logits (128 threads, one (g, pos) each, 128-dot via float4)
        if (t < 128) {
            int g = t & 3, i = t >> 2;
            int pos = p0 + i;
            float lg = -1e30f;
            if (pos < ctx) {
                float sum = 0.f;
#pragma unroll
                for (int j = 0; j < 32; j++) {
                    float4 qv = *(const float4*)&q_s[g][j * 4];
                    float4 kv = *(const float4*)&k_s[i][j * 4];
                    sum += qv.x * kv.x + qv.y * kv.y + qv.z * kv.z + qv.w * kv.w;
                }
                lg = sum;
            }
            logit_s[g][i] = lg;
        }
        __syncthreads();

        // phase 2a: chunk max + probs
        if (t < 128) {
            int g = t & 3, i = t >> 2;
            float cmax = -INFINITY;
#pragma unroll
            for (int ii = 0; ii < 32; ii++) cmax = fmaxf(cmax, logit_s[g][ii]);
            float newm = fmaxf(m_sh[g], cmax);
            float lg = logit_s[g][i];
            prob_s[g][i] = (lg > -1e29f) ? expf(lg - newm) : 0.f;
            if (i == 0) { newm_sh[g] = newm; corr_sh[g] = expf(m_sh[g] - newm); }
        }
        __syncthreads();

        // phase 2b: rescale + accumulate AV (all 256 threads)
        {
            float corr = corr_sh[g2];
            acc0 *= corr; acc1 *= corr; lsum *= corr;
            float psum = 0.f;
#pragma unroll
            for (int i = 0; i < 32; i++) {
                float p = prob_s[g2][i];
                psum += p;
                float2 vv = *(const float2*)&v_s[i][hh * 2];
                acc0 += p * vv.x;
                acc1 += p * vv.y;
            }
            lsum += psum;
            if (hh == 0) m_sh[g2] = newm_sh[g2];
        }
        __syncthreads();
    }

    float inv = 1.0f / lsum;
    int n = kvh * 4 + g2;
    *(float2*)&g_obuf[((size_t)b * 32 + n) * 128 + hh * 2] = make_float2(acc0 * inv, acc1 * inv);
}

// ---------------- Kernel 5: O projection (M=64, N=4096, K=4096; K-split 4) ----------------
// grid = 64 d-tiles * 4 k-splits, 256 threads, 64x64 tile per block over K=1024.
__global__ __launch_bounds__(256) void o_gemm(const float* __restrict__ o_w)
{
    int nt = blockIdx.x >> 2;  // d-tile 0..63
    int ks = blockIdx.x & 3;
    int d0 = nt * 64;
    int k0 = ks * 1024;

    __shared__ float as_[64][36];
    __shared__ float ws[32][68];

    int t = threadIdx.x;
    int ty = t >> 4, tx = t & 15;
    float acc[4][4];
#pragma unroll
    for (int i = 0; i < 4; i++)
#pragma unroll
        for (int j = 0; j < 4; j++) acc[i][j] = 0.f;

    for (int kt = 0; kt < 1024; kt += 32) {
#pragma unroll
        for (int r = 0; r < 2; r++) {
            int f = t + 256 * r;
            int row = f >> 3, q4 = f & 7;
            *(float4*)&as_[row][q4 * 4] =
                *(const float4*)(g_obuf + (size_t)row * DMODEL + k0 + kt + q4 * 4);
        }
#pragma unroll
        for (int r = 0; r < 2; r++) {
            int f = t + 256 * r;
            int row = f >> 4, q4 = f & 15;
            *(float4*)&ws[row][q4 * 4] =
                *(const float4*)(o_w + (size_t)(k0 + kt + row) * DMODEL + d0 + q4 * 4);
        }
        __syncthreads();
#pragma unroll
        for (int kk = 0; kk < 32; kk++) {
            float a0 = as_[ty * 4 + 0][kk];
            float a1 = as_[ty * 4 + 1][kk];
            float a2 = as_[ty * 4 + 2][kk];
            float a3 = as_[ty * 4 + 3][kk];
            float4 bv = *(const float4*)&ws[kk][tx * 4];
            acc[0][0] += a0 * bv.x; acc[0][1] += a0 * bv.y; acc[0][2] += a0 * bv.z; acc[0][3] += a0 * bv.w;
            acc[1][0] += a1 * bv.x; acc[1][1] += a1 * bv.y; acc[1][2] += a1 * bv.z; acc[1][3] += a1 * bv.w;
            acc[2][0] += a2 * bv.x; acc[2][1] += a2 * bv.y; acc[2][2] += a2 * bv.z; acc[2][3] += a2 * bv.w;
            acc[3][0] += a3 * bv.x; acc[3][1] += a3 * bv.y; acc[3][2] += a3 * bv.z; acc[3][3] += a3 * bv.w;
        }
        __syncthreads();
    }

    float* dst = g_opart + (size_t)ks * BATCH * DMODEL;
#pragma unroll
    for (int i = 0; i < 4; i++) {
        *(float4*)&dst[(size_t)(ty * 4 + i) * DMODEL + d0 + tx * 4] =
            make_float4(acc[i][0], acc[i][1], acc[i][2], acc[i][3]);
    }
}

// ---------------- Kernel 6: reduce the 4 K-split partials into d_out ----------------
__global__ void o_reduce(float* __restrict__ out_attn)
{
    int i = blockIdx.x * 256 + threadIdx.x;  // < 262144
    float s = g_opart[i]
            + g_opart[i + BATCH * DMODEL]
            + g_opart[i + 2 * BATCH * DMODEL]
            + g_opart[i + 3 * BATCH * DMODEL];
    out_attn[i] = s;
}

// ---------------- launch ----------------
extern "C" void kernel_launch(void* const* d_in, const int* in_sizes, int n_in,
                              void* d_out, int out_size)
{
    const float* x            = (const float*)d_in[0];
    // d_in[1] = segment_pos (== context_lens - 1, unused)
    const int*   slot_mapping = (const int*)d_in[2];
    const int*   block_tables = (const int*)d_in[3];
    const int*   context_lens = (const int*)d_in[4];
    const float* cache        = (const float*)d_in[5];
    const float* q_w          = (const float*)d_in[6];
    const float* kv_w         = (const float*)d_in[7];
    const float* o_w          = (const float*)d_in[8];
    float* out = (float*)d_out;

    // 1) full cache copy into the output (537 MB, D2D memcpy node)
    cudaMemcpyAsync(out, cache, 2L * CACHE_HALF * sizeof(float),
                    cudaMemcpyDeviceToDevice, 0);

    // 2) QKV projection + rope
    qkv_gemm<<<NMAT * KSPLIT, 256>>>(x, q_w, kv_w);
    reduce_rope<<<(NMAT * BATCH * 64 + 255) / 256, 256>>>(context_lens);

    // 3) scatter the new k/v rows into the output cache
    cache_scatter<<<BATCH, 256>>>(slot_mapping, out);

    // 4) paged attention (reads original cache + fresh k/v for pos ctx-1)
    attn_kernel<<<BATCH * KVHEADS, 256>>>(cache, block_tables, context_lens);

    // 5) output projection + K-split reduce
    o_gemm<<<64 * 4, 256>>>(o_w);
    o_reduce<<<(BATCH * DMODEL) / 256, 256>>>(out + ATTN_OUT_OFF);
}

// round 14
// speedup vs baseline: 1.0028x; 1.0028x over previous
#include <cuda_runtime.h>
#include <math.h>

#define BATCH 64
#define DMODEL 4096
#define NHEADS 32
#define KVHEADS 8
#define HDIM 128
#define NMAT 48              // 32 q mats + 8 k mats + 8 v mats, each D x H
#define KSPLIT 8
#define KCHUNK (DMODEL / KSPLIT)   // 512
#define CACHE_HALF 67108864L       // 65536 * 8 * 128
#define ATTN_OUT_OFF 134217728L    // 2 * CACHE_HALF

// ---------------- scratch (allocation-free, __device__ globals) ----------------
__device__ __align__(16) float g_qkv_part[NMAT * KSPLIT * BATCH * HDIM]; // 12.6 MB
__device__ __align__(16) float g_qbuf[BATCH * NHEADS * HDIM];
__device__ __align__(16) float g_kbuf[BATCH * KVHEADS * HDIM];
__device__ __align__(16) float g_vbuf[BATCH * KVHEADS * HDIM];
__device__ __align__(16) float g_obuf[BATCH * NHEADS * HDIM];
__device__ __align__(16) float g_opart[4 * BATCH * DMODEL];              // 4 MB

// ---------------- Kernel 1: QKV projection (48 DxH mats, K-split 8) ----------------
// grid = 48*8 blocks, 256 threads. Block computes 64(b) x 128(h) partial over 512 K.
__global__ __launch_bounds__(256) void qkv_gemm(
    const float* __restrict__ x,      // (64, 4096)
    const float* __restrict__ q_w,    // (32, 4096, 128)
    const float* __restrict__ kv_w)   // (2, 8, 4096, 128) -> 16 mats
{
    int mat = blockIdx.x >> 3;
    int ks  = blockIdx.x & 7;
    const float* W = (mat < 32) ? (q_w  + (size_t)mat * DMODEL * HDIM)
                                : (kv_w + (size_t)(mat - 32) * DMODEL * HDIM);
    int d0 = ks * KCHUNK;

    __shared__ float xs[64][36];    // 64 b x 32 k, pad 36 (16B-aligned rows)
    __shared__ float ws[32][132];   // 32 k x 128 h, pad 132

    int t  = threadIdx.x;
    int ty = t >> 4;   // 0..15 -> m tile
    int tx = t & 15;   // 0..15 -> h tile

    float acc[4][8];
#pragma unroll
    for (int i = 0; i < 4; i++)
#pragma unroll
        for (int j = 0; j < 8; j++) acc[i][j] = 0.f;

    for (int dt = 0; dt < KCHUNK; dt += 32) {
        // load x tile: 64 rows x 32 floats = 512 float4
#pragma unroll
        for (int r = 0; r < 2; r++) {
            int f = t + 256 * r;
            int row = f >> 3, q4 = f & 7;
            float4 v = *(const float4*)(x + (size_t)row * DMODEL + d0 + dt + q4 * 4);
            *(float4*)&xs[row][q4 * 4] = v;
        }
        // load W tile: 32 rows x 128 floats = 1024 float4
#pragma unroll
        for (int r = 0; r < 4; r++) {
            int f = t + 256 * r;
            int row = f >> 5, q4 = f & 31;
            float4 v = *(const float4*)(W + (size_t)(d0 + dt + row) * HDIM + q4 * 4);
            *(float4*)&ws[row][q4 * 4] = v;
        }
        __syncthreads();
#pragma unroll
        for (int kk = 0; kk < 32; kk++) {
            float a0 = xs[ty * 4 + 0][kk];
            float a1 = xs[ty * 4 + 1][kk];
            float a2 = xs[ty * 4 + 2][kk];
            float a3 = xs[ty * 4 + 3][kk];
            float4 b0 = *(const float4*)&ws[kk][tx * 8];
            float4 b1 = *(const float4*)&ws[kk][tx * 8 + 4];
            acc[0][0] += a0 * b0.x; acc[0][1] += a0 * b0.y; acc[0][2] += a0 * b0.z; acc[0][3] += a0 * b0.w;
            acc[0][4] += a0 * b1.x; acc[0][5] += a0 * b1.y; acc[0][6] += a0 * b1.z; acc[0][7] += a0 * b1.w;
            acc[1][0] += a1 * b0.x; acc[1][1] += a1 * b0.y; acc[1][2] += a1 * b0.z; acc[1][3] += a1 * b0.w;
            acc[1][4] += a1 * b1.x; acc[1][5] += a1 * b1.y; acc[1][6] += a1 * b1.z; acc[1][7] += a1 * b1.w;
            acc[2][0] += a2 * b0.x; acc[2][1] += a2 * b0.y; acc[2][2] += a2 * b0.z; acc[2][3] += a2 * b0.w;
            acc[2][4] += a2 * b1.x; acc[2][5] += a2 * b1.y; acc[2][6] += a2 * b1.z; acc[2][7] += a2 * b1.w;
            acc[3][0] += a3 * b0.x; acc[3][1] += a3 * b0.y; acc[3][2] += a3 * b0.z; acc[3][3] += a3 * b0.w;
            acc[3][4] += a3 * b1.x; acc[3][5] += a3 * b1.y; acc[3][6] += a3 * b1.z; acc[3][7] += a3 * b1.w;
        }
        __syncthreads();
    }

    float* dst = g_qkv_part + ((size_t)(mat * 8 + ks) * 64) * 128;
#pragma unroll
    for (int i = 0; i < 4; i++) {
        int row = ty * 4 + i;
        *(float4*)&dst[row * 128 + tx * 8]     = make_float4(acc[i][0], acc[i][1], acc[i][2], acc[i][3]);
        *(float4*)&dst[row * 128 + tx * 8 + 4] = make_float4(acc[i][4], acc[i][5], acc[i][6], acc[i][7]);
    }
}

// ---------------- Kernel 2: reduce K-split partials + RoPE ----------------
// one thread per (mat, b, j) with j < 64 (rotation pair j, j+64)
__global__ __launch_bounds__(256) void reduce_rope(const int* __restrict__ context_lens)
{
    int tid = blockIdx.x * 256 + threadIdx.x;
    if (tid >= NMAT * BATCH * 64) return;
    int mat = tid >> 12;
    int rem = tid & 4095;
    int b = rem >> 6;
    int j = rem & 63;

    float v1 = 0.f, v2 = 0.f;
    size_t off = ((size_t)(mat * 8) * 64 + b) * 128;
#pragma unroll
    for (int ks = 0; ks < 8; ks++) {
        v1 += g_qkv_part[off + j];
        v2 += g_qkv_part[off + 64 + j];
        off += 64 * 128;
    }

    float o1 = v1, o2 = v2;
    if (mat < 40) {  // rope on q (0..31) and k (32..39), not v
        float pos = (float)(context_lens[b] - 1);
        float ts = powf(10000.0f, (float)j * (1.0f / 64.0f));
        float ang = pos / ts;
        float s = sinf(ang), c = cosf(ang);
        o1 = v1 * c - v2 * s;
        o2 = v2 * c + v1 * s;
    }

    if (mat < 32) {
        float* d = g_qbuf + ((size_t)b * 32 + mat) * 128;
        d[j] = o1; d[j + 64] = o2;
    } else if (mat < 40) {
        float* d = g_kbuf + ((size_t)b * 8 + (mat - 32)) * 128;
        d[j] = o1; d[j + 64] = o2;
    } else {
        float* d = g_vbuf + ((size_t)b * 8 + (mat - 40)) * 128;
        d[j] = o1; d[j + 64] = o2;
    }
}

// ---------------- Kernel 3: scatter new k/v rows into the output cache ----------------
__global__ void cache_scatter(const int* __restrict__ slot_mapping, float* __restrict__ out)
{
    int b = blockIdx.x;
    int slot = slot_mapping[b];
    int t = threadIdx.x;  // 256 threads, 256 float4 per (k,v) row group of 1024 floats
    const float4* ksrc = (const float4*)(g_kbuf + (size_t)b * 1024);
    const float4* vsrc = (const float4*)(g_vbuf + (size_t)b * 1024);
    float4* dk = (float4*)(out + (size_t)slot * 1024);
    float4* dv = (float4*)(out + CACHE_HALF + (size_t)slot * 1024);
    dk[t] = ksrc[t];
    dv[t] = vsrc[t];
}

// ---------------- Kernel 4: paged attention (online softmax, chunk=32) ----------------
// grid = 64*8 blocks (b, kv-head), 256 threads, G=4 query heads per block.
__global__ __launch_bounds__(256) void attn_kernel(
    const float* __restrict__ cache,        // (2, 65536, 8, 128) ORIGINAL
    const int*   __restrict__ block_tables, // (64, 64)
    const int*   __restrict__ context_lens) // (64,)
{
    int b   = blockIdx.x >> 3;
    int kvh = blockIdx.x & 7;
    int t = threadIdx.x;

    __shared__ float q_s[4][132];
    __shared__ float k_s[32][132];
    __shared__ float v_s[32][132];
    __shared__ float logit_s[4][32];
    __shared__ float prob_s[4][32];
    __shared__ float m_sh[4], newm_sh[4], corr_sh[4];
    __shared__ int   bt_s[64];

    int ctx = context_lens[b];
    if (t < 64) bt_s[t] = block_tables[b * 64 + t];

    const float sm_scale = 0.08838834764831845f;  // 128^-0.5
#pragma unroll
    for (int r = 0; r < 2; r++) {
        int f = t + 256 * r;
        int g = f >> 7, h = f & 127;
        q_s[g][h] = g_qbuf[((size_t)b * 32 + kvh * 4 + g) * 128 + h] * sm_scale;
    }
    if (t < 4) m_sh[t] = -INFINITY;

    float acc0 = 0.f, acc1 = 0.f, lsum = 0.f;
    int g2 = t >> 6;    // 0..3 accumulation head
    int hh = t & 63;    // output pair index
    __syncthreads();

    const float* kc = cache;
    const float* vc = cache + CACHE_HALF;

    int nchunk = (ctx + 31) >> 5;
    for (int c = 0; c < nchunk; c++) {
        int p0 = c << 5;
        // load K/V chunk: 32 pos x 128 floats each = 1024 float4 per tensor
#pragma unroll
        for (int r = 0; r < 4; r++) {
            int f = t + 256 * r;
            int row = f >> 5;        // 0..31
            int q4  = f & 31;
            int pos = p0 + row;
            float4 kval = make_float4(0.f, 0.f, 0.f, 0.f);
            float4 vval = kval;
            if (pos < ctx) {
                if (pos == ctx - 1) {
                    kval = *(const float4*)(g_kbuf + ((size_t)b * 8 + kvh) * 128 + q4 * 4);
                    vval = *(const float4*)(g_vbuf + ((size_t)b * 8 + kvh) * 128 + q4 * 4);
                } else {
                    int slot = bt_s[pos >> 4] * 16 + (pos & 15);
                    size_t off = (size_t)slot * 1024 + kvh * 128 + q4 * 4;
                    kval = *(const float4*)(kc + off);
                    vval = *(const float4*)(vc + off);
                }
            }
            *(float4*)&k_s[row][q4 * 4] = kval;
            *(float4*)&v_s[row][q4 * 4] = vval;
        }
        __syncthreads();

        // phase 1: logits (128 threads, one (g, pos) each, 128-dot via float4)
        if (t < 128) {
            int g = t & 3, i = t >> 2;
            int pos = p0 + i;
            float lg = -1e30f;
            if (pos < ctx) {
                float sum = 0.f;
#pragma unroll
                for (int j = 0; j < 32; j++) {
                    float4 qv = *(const float4*)&q_s[g][j * 4];
                    float4 kv = *(const float4*)&k_s[i][j * 4];
                    sum += qv.x * kv.x + qv.y * kv.y + qv.z * kv.z + qv.w * kv.w;
                }
                lg = sum;
            }
            logit_s[g][i] = lg;
        }
        __syncthreads();

        // phase 2a: chunk max + probs
        if (t < 128) {
            int g = t & 3, i = t >> 2;
            float cmax = -INFINITY;
#pragma unroll
            for (int ii = 0; ii < 32; ii++) cmax = fmaxf(cmax, logit_s[g][ii]);
            float newm = fmaxf(m_sh[g], cmax);
            float lg = logit_s[g][i];
            prob_s[g][i] = (lg > -1e29f) ? expf(lg - newm) : 0.f;
            if (i == 0) { newm_sh[g] = newm; corr_sh[g] = expf(m_sh[g] - newm); }
        }
        __syncthreads();

        // phase 2b: rescale + accumulate AV (all 256 threads)
        {
            float corr = corr_sh[g2];
            acc0 *= corr; acc1 *= corr; lsum *= corr;
            float psum = 0.f;
#pragma unroll
            for (int i = 0; i < 32; i++) {
                float p = prob_s[g2][i];
                psum += p;
                float2 vv = *(const float2*)&v_s[i][hh * 2];
                acc0 += p * vv.x;
                acc1 += p * vv.y;
            }
            lsum += psum;
            if (hh == 0) m_sh[g2] = newm_sh[g2];
        }
        __syncthreads();
    }

    float inv = 1.0f / lsum;
    int n = kvh * 4 + g2;
    *(float2*)&g_obuf[((size_t)b * 32 + n) * 128 + hh * 2] = make_float2(acc0 * inv, acc1 * inv);
}

// ---------------- Kernel 5: O projection (M=64, N=4096, K=4096; K-split 4) ----------------
// grid = 64 d-tiles * 4 k-splits, 256 threads, 64x64 tile per block over K=1024.
__global__ __launch_bounds__(256) void o_gemm(const float* __restrict__ o_w)
{
    int nt = blockIdx.x >> 2;  // d-tile 0..63
    int ks = blockIdx.x & 3;
    int d0 = nt * 64;
    int k0 = ks * 1024;

    __shared__ float as_[64][36];
    __shared__ float ws[32][68];

    int t = threadIdx.x;
    int ty = t >> 4, tx = t & 15;
    float acc[4][4];
#pragma unroll
    for (int i = 0; i < 4; i++)
#pragma unroll
        for (int j = 0; j < 4; j++) acc[i][j] = 0.f;

    for (int kt = 0; kt < 1024; kt += 32) {
#pragma unroll
        for (int r = 0; r < 2; r++) {
            int f = t + 256 * r;
            int row = f >> 3, q4 = f & 7;
            *(float4*)&as_[row][q4 * 4] =
                *(const float4*)(g_obuf + (size_t)row * DMODEL + k0 + kt + q4 * 4);
        }
#pragma unroll
        for (int r = 0; r < 2; r++) {
            int f = t + 256 * r;
            int row = f >> 4, q4 = f & 15;
            *(float4*)&ws[row][q4 * 4] =
                *(const float4*)(o_w + (size_t)(k0 + kt + row) * DMODEL + d0 + q4 * 4);
        }
        __syncthreads();
#pragma unroll
        for (int kk = 0; kk < 32; kk++) {
            float a0 = as_[ty * 4 + 0][kk];
            float a1 = as_[ty * 4 + 1][kk];
            float a2 = as_[ty * 4 + 2][kk];
            float a3 = as_[ty * 4 + 3][kk];
            float4 bv = *(const float4*)&ws[kk][tx * 4];
            acc[0][0] += a0 * bv.x; acc[0][1] += a0 * bv.y; acc[0][2] += a0 * bv.z; acc[0][3] += a0 * bv.w;
            acc[1][0] += a1 * bv.x; acc[1][1] += a1 * bv.y; acc[1][2] += a1 * bv.z; acc[1][3] += a1 * bv.w;
            acc[2][0] += a2 * bv.x; acc[2][1] += a2 * bv.y; acc[2][2] += a2 * bv.z; acc[2][3] += a2 * bv.w;
            acc[3][0] += a3 * bv.x; acc[3][1] += a3 * bv.y; acc[3][2] += a3 * bv.z; acc[3][3] += a3 * bv.w;
        }
        __syncthreads();
    }

    float* dst = g_opart + (size_t)ks * BATCH * DMODEL;
#pragma unroll
    for (int i = 0; i < 4; i++) {
        *(float4*)&dst[(size_t)(ty * 4 + i) * DMODEL + d0 + tx * 4] =
            make_float4(acc[i][0], acc[i][1], acc[i][2], acc[i][3]);
    }
}

// ---------------- Kernel 6: reduce the 4 K-split partials into d_out ----------------
__global__ void o_reduce(float* __restrict__ out_attn)
{
    int i = blockIdx.x * 256 + threadIdx.x;  // < 262144
    float s = g_opart[i]
            + g_opart[i + BATCH * DMODEL]
            + g_opart[i + 2 * BATCH * DMODEL]
            + g_opart[i + 3 * BATCH * DMODEL];
    out_attn[i] = s;
}

// ---------------- launch ----------------
extern "C" void kernel_launch(void* const* d_in, const int* in_sizes, int n_in,
                              void* d_out, int out_size)
{
    const float* x            = (const float*)d_in[0];
    // d_in[1] = segment_pos (== context_lens - 1, unused)
    const int*   slot_mapping = (const int*)d_in[2];
    const int*   block_tables = (const int*)d_in[3];
    const int*   context_lens = (const int*)d_in[4];
    const float* cache        = (const float*)d_in[5];
    const float* q_w          = (const float*)d_in[6];
    const float* kv_w         = (const float*)d_in[7];
    const float* o_w          = (const float*)d_in[8];
    float* out = (float*)d_out;

    // 1) full cache copy into the output (537 MB, D2D memcpy node)
    cudaMemcpyAsync(out, cache, 2L * CACHE_HALF * sizeof(float),
                    cudaMemcpyDeviceToDevice, 0);

    // 2) QKV projection + rope
    qkv_gemm<<<NMAT * KSPLIT, 256>>>(x, q_w, kv_w);
    reduce_rope<<<(NMAT * BATCH * 64 + 255) / 256, 256>>>(context_lens);

    // 3) scatter the new k/v rows into the output cache
    cache_scatter<<<BATCH, 256>>>(slot_mapping, out);

    // 4) paged attention (reads original cache + fresh k/v for pos ctx-1)
    attn_kernel<<<BATCH * KVHEADS, 256>>>(cache, block_tables, context_lens);

    // 5) output projection + K-split reduce
    o_gemm<<<64 * 4, 256>>>(o_w);
    o_reduce<<<(BATCH * DMODEL) / 256, 256>>>(out + ATTN_OUT_OFF);
}

// round 15
// speedup vs baseline: 1.5901x; 1.5856x over previous
#include <cuda_runtime.h>
#include <math.h>

#define BATCH 64
#define DMODEL 4096
#define NHEADS 32
#define KVHEADS 8
#define HDIM 128
#define NMAT 48
#define KSPLIT 8
#define KCHUNK (DMODEL / KSPLIT)   // 512
#define CACHE_HALF 67108864L       // 65536 * 8 * 128
#define ATTN_OUT_OFF 134217728L    // 2 * CACHE_HALF
#define ASPLIT 4                   // attention KV splits (256 positions each)
#define TOTAL_ROWS 131072L         // 2 * 65536 cache rows of 1024 floats
#define ROWS_PER_COPY 64
#define NCOPY 2048                 // total copy blocks
#define NCOPY_QKV 1024
#define NCOPY_ATTN 640
#define NCOPY_O 384

// ---------------- scratch (allocation-free, __device__ globals) ----------------
__device__ __align__(16) float g_qkv_part[NMAT * KSPLIT * BATCH * HDIM]; // 12.6 MB
__device__ __align__(16) float g_qbuf[BATCH * NHEADS * HDIM];
__device__ __align__(16) float g_kbuf[BATCH * KVHEADS * HDIM];
__device__ __align__(16) float g_vbuf[BATCH * KVHEADS * HDIM];
__device__ __align__(16) float g_obuf[BATCH * NHEADS * HDIM];
__device__ __align__(16) float g_opart[4 * BATCH * DMODEL];              // 4 MB
__device__ __align__(16) float g_apart[BATCH * KVHEADS * ASPLIT * 520]; // 4.3 MB

// ---------------- cp.async helpers ----------------
__device__ __forceinline__ void cp_async16(void* dst, const void* src) {
    unsigned d = (unsigned)__cvta_generic_to_shared(dst);
    asm volatile("cp.async.cg.shared.global [%0], [%1], 16;\n" :: "r"(d), "l"(src));
}
__device__ __forceinline__ void cp_commit_wait_all() {
    asm volatile("cp.async.commit_group;\ncp.async.wait_group 0;\n" ::: "memory");
}

// ---------------- shared copy path: copy 64 cache rows, skipping scatter slots ----------------
__device__ __forceinline__ void copy_rows(int cid,
                                          const float* __restrict__ cache,
                                          const int* __restrict__ slot_mapping,
                                          float* __restrict__ out,
                                          int* s_slots, int* s_skip)
{
    int t = threadIdx.x;
    if (t < 64) s_slots[t] = slot_mapping[t];
    __syncthreads();
    long r0 = (long)cid << 6;                  // 64 rows per block, same cache half
    if (t < 64) {
        int slot = (int)((r0 + t) & 65535L);
        int sk = 0;
#pragma unroll 8
        for (int i = 0; i < 64; i++) sk |= (s_slots[i] == slot);
        s_skip[t] = sk;
    }
    __syncthreads();
    const float4* src = (const float4*)cache + (r0 << 8) + t;  // 256 float4 per row
    float4*       dst = (float4*)out         + (r0 << 8) + t;
#pragma unroll 8
    for (int it = 0; it < 64; it++) {
        if (!s_skip[it]) dst[it * 256] = src[it * 256];
    }
}

// ---------------- Kernel 1: QKV projection + 1024 copy blocks ----------------
__global__ __launch_bounds__(256) void qkv_copy_kernel(
    const float* __restrict__ x,
    const float* __restrict__ q_w,
    const float* __restrict__ kv_w,
    const float* __restrict__ cache,
    const int*   __restrict__ slot_mapping,
    float*       __restrict__ out)
{
    __shared__ __align__(16) float xs[64][36];
    __shared__ __align__(16) float ws[32][132];
    __shared__ int s_slots[64];
    __shared__ int s_skip[64];

    int bid = blockIdx.x;
    if (bid >= NMAT * KSPLIT) {                 // copy block
        copy_rows(bid - NMAT * KSPLIT, cache, slot_mapping, out, s_slots, s_skip);
        return;
    }
    int mat = bid >> 3;
    int ks  = bid & 7;
    const float* W = (mat < 32) ? (q_w  + (size_t)mat * DMODEL * HDIM)
                                : (kv_w + (size_t)(mat - 32) * DMODEL * HDIM);
    int d0 = ks * KCHUNK;

    int t  = threadIdx.x;
    int ty = t >> 4;
    int tx = t & 15;

    float acc[4][8];
#pragma unroll
    for (int i = 0; i < 4; i++)
#pragma unroll
        for (int j = 0; j < 8; j++) acc[i][j] = 0.f;

    for (int dt = 0; dt < KCHUNK; dt += 32) {
#pragma unroll
        for (int r = 0; r < 2; r++) {
            int f = t + 256 * r;
            int row = f >> 3, q4 = f & 7;
            *(float4*)&xs[row][q4 * 4] =
                *(const float4*)(x + (size_t)row * DMODEL + d0 + dt + q4 * 4);
        }
#pragma unroll
        for (int r = 0; r < 4; r++) {
            int f = t + 256 * r;
            int row = f >> 5, q4 = f & 31;
            *(float4*)&ws[row][q4 * 4] =
                *(const float4*)(W + (size_t)(d0 + dt + row) * HDIM + q4 * 4);
        }
        __syncthreads();
#pragma unroll
        for (int kk = 0; kk < 32; kk++) {
            float a0 = xs[ty * 4 + 0][kk];
            float a1 = xs[ty * 4 + 1][kk];
            float a2 = xs[ty * 4 + 2][kk];
            float a3 = xs[ty * 4 + 3][kk];
            float4 b0 = *(const float4*)&ws[kk][tx * 8];
            float4 b1 = *(const float4*)&ws[kk][tx * 8 + 4];
            acc[0][0] += a0 * b0.x; acc[0][1] += a0 * b0.y; acc[0][2] += a0 * b0.z; acc[0][3] += a0 * b0.w;
            acc[0][4] += a0 * b1.x; acc[0][5] += a0 * b1.y; acc[0][6] += a0 * b1.z; acc[0][7] += a0 * b1.w;
            acc[1][0] += a1 * b0.x; acc[1][1] += a1 * b0.y; acc[1][2] += a1 * b0.z; acc[1][3] += a1 * b0.w;
            acc[1][4] += a1 * b1.x; acc[1][5] += a1 * b1.y; acc[1][6] += a1 * b1.z; acc[1][7] += a1 * b1.w;
            acc[2][0] += a2 * b0.x; acc[2][1] += a2 * b0.y; acc[2][2] += a2 * b0.z; acc[2][3] += a2 * b0.w;
            acc[2][4] += a2 * b1.x; acc[2][5] += a2 * b1.y; acc[2][6] += a2 * b1.z; acc[2][7] += a2 * b1.w;
            acc[3][0] += a3 * b0.x; acc[3][1] += a3 * b0.y; acc[3][2] += a3 * b0.z; acc[3][3] += a3 * b0.w;
            acc[3][4] += a3 * b1.x; acc[3][5] += a3 * b1.y; acc[3][6] += a3 * b1.z; acc[3][7] += a3 * b1.w;
        }
        __syncthreads();
    }

    float* dst = g_qkv_part + ((size_t)(mat * 8 + ks) * 64) * 128;
#pragma unroll
    for (int i = 0; i < 4; i++) {
        int row = ty * 4 + i;
        *(float4*)&dst[row * 128 + tx * 8]     = make_float4(acc[i][0], acc[i][1], acc[i][2], acc[i][3]);
        *(float4*)&dst[row * 128 + tx * 8 + 4] = make_float4(acc[i][4], acc[i][5], acc[i][6], acc[i][7]);
    }
}

// ---------------- Kernel 2: reduce K-split partials + RoPE ----------------
__global__ __launch_bounds__(256) void reduce_rope(const int* __restrict__ context_lens)
{
    int tid = blockIdx.x * 256 + threadIdx.x;
    if (tid >= NMAT * BATCH * 64) return;
    int mat = tid >> 12;
    int rem = tid & 4095;
    int b = rem >> 6;
    int j = rem & 63;

    float v1 = 0.f, v2 = 0.f;
    size_t off = ((size_t)(mat * 8) * 64 + b) * 128;
#pragma unroll
    for (int ks = 0; ks < 8; ks++) {
        v1 += g_qkv_part[off + j];
        v2 += g_qkv_part[off + 64 + j];
        off += 64 * 128;
    }

    float o1 = v1, o2 = v2;
    if (mat < 40) {
        float pos = (float)(context_lens[b] - 1);
        float ts = powf(10000.0f, (float)j * (1.0f / 64.0f));
        float ang = pos / ts;
        float s = sinf(ang), c = cosf(ang);
        o1 = v1 * c - v2 * s;
        o2 = v2 * c + v1 * s;
    }

    if (mat < 32) {
        float* d = g_qbuf + ((size_t)b * 32 + mat) * 128;
        d[j] = o1; d[j + 64] = o2;
    } else if (mat < 40) {
        float* d = g_kbuf + ((size_t)b * 8 + (mat - 32)) * 128;
        d[j] = o1; d[j + 64] = o2;
    } else {
        float* d = g_vbuf + ((size_t)b * 8 + (mat - 40)) * 128;
        d[j] = o1; d[j + 64] = o2;
    }
}

// ---------------- Kernel 3: write the new k/v rows (copy blocks skipped these) ----------------
__global__ void cache_scatter(const int* __restrict__ slot_mapping, float* __restrict__ out)
{
    int b = blockIdx.x;
    int slot = slot_mapping[b];
    int t = threadIdx.x;
    const float4* ksrc = (const float4*)(g_kbuf + (size_t)b * 1024);
    const float4* vsrc = (const float4*)(g_vbuf + (size_t)b * 1024);
    float4* dk = (float4*)(out + (size_t)slot * 1024);
    float4* dv = (float4*)(out + CACHE_HALF + (size_t)slot * 1024);
    dk[t] = ksrc[t];
    dv[t] = vsrc[t];
}

// ---------------- Kernel 4: split-KV attention + 640 copy blocks ----------------
// attn blocks: aid = b*32 + kvh*4 + sp; each handles positions [sp*256, sp*256+256)
__global__ __launch_bounds__(256) void attn_copy_kernel(
    const float* __restrict__ cache,
    const int*   __restrict__ block_tables,
    const int*   __restrict__ context_lens,
    const int*   __restrict__ slot_mapping,
    float*       __restrict__ out)
{
    __shared__ __align__(16) float q_s[4][132];
    __shared__ __align__(16) float k_s[32][132];
    __shared__ __align__(16) float v_s[32][132];
    __shared__ float logit_s[4][32];
    __shared__ float prob_s[4][32];
    __shared__ float m_sh[4], newm_sh[4], corr_sh[4];
    __shared__ int   bt_s[16];
    __shared__ int   s_slots[64];
    __shared__ int   s_skip[64];

    int bid = blockIdx.x;
    int grp = bid / 21, lane = bid % 21;       // 16 attn + 5 copy per group of 21
    if (lane >= 16) {
        copy_rows(NCOPY_QKV + grp * 5 + (lane - 16), cache, slot_mapping, out, s_slots, s_skip);
        return;
    }
    int aid = grp * 16 + lane;
    int b   = aid >> 5;
    int kvh = (aid >> 2) & 7;
    int sp  = aid & 3;
    int t = threadIdx.x;

    int ctx = context_lens[b];
    int start = sp << 8;
    long pbase = (long)aid * 520;
    if (start >= ctx) {
        if (t < 4) {
            g_apart[pbase + 512 + t] = -INFINITY;
            g_apart[pbase + 516 + t] = 0.f;
        }
        return;
    }
    int end = min(ctx, start + 256);

    if (t < 16) bt_s[t] = block_tables[b * 64 + sp * 16 + t];

    const float sm_scale = 0.08838834764831845f;
#pragma unroll
    for (int r = 0; r < 2; r++) {
        int f = t + 256 * r;
        int g = f >> 7, h = f & 127;
        q_s[g][h] = g_qbuf[((size_t)b * 32 + kvh * 4 + g) * 128 + h] * sm_scale;
    }
    if (t < 4) m_sh[t] = -INFINITY;

    float acc0 = 0.f, acc1 = 0.f, lsum = 0.f;
    int g2 = t >> 6;
    int hh = t & 63;
    __syncthreads();

    const float* kc = cache;
    const float* vc = cache + CACHE_HALF;

    int nchunk = (end - start + 31) >> 5;
    for (int c = 0; c < nchunk; c++) {
        int p0 = start + (c << 5);
        // async load of K/V chunk (32 positions x 128 floats each)
#pragma unroll
        for (int r = 0; r < 4; r++) {
            int f = t + 256 * r;
            int row = f >> 5;
            int q4  = f & 31;
            int pos = p0 + row;
            int posc = min(pos, ctx - 1);
            const float* ks;
            const float* vs;
            if (posc == ctx - 1) {
                ks = g_kbuf + ((size_t)b * 8 + kvh) * 128 + q4 * 4;
                vs = g_vbuf + ((size_t)b * 8 + kvh) * 128 + q4 * 4;
            } else {
                int slot = bt_s[(posc >> 4) & 15] * 16 + (posc & 15);
                size_t off = (size_t)slot * 1024 + kvh * 128 + q4 * 4;
                ks = kc + off;
                vs = vc + off;
            }
            cp_async16(&k_s[row][q4 * 4], ks);
            cp_async16(&v_s[row][q4 * 4], vs);
        }
        cp_commit_wait_all();
        __syncthreads();

        // phase 1: logits
        if (t < 128) {
            int g = t & 3, i = t >> 2;
            int pos = p0 + i;
            float lg = -1e30f;
            if (pos < ctx) {
                float sum = 0.f;
#pragma unroll
                for (int j = 0; j < 32; j++) {
                    float4 qv = *(const float4*)&q_s[g][j * 4];
                    float4 kv = *(const float4*)&k_s[i][j * 4];
                    sum += qv.x * kv.x + qv.y * kv.y + qv.z * kv.z + qv.w * kv.w;
                }
                lg = sum;
            }
            logit_s[g][i] = lg;
        }
        __syncthreads();

        // phase 2a: chunk max + probs
        if (t < 128) {
            int g = t & 3, i = t >> 2;
            float cmax = -INFINITY;
#pragma unroll
            for (int ii = 0; ii < 32; ii++) cmax = fmaxf(cmax, logit_s[g][ii]);
            float newm = fmaxf(m_sh[g], cmax);
            float lg = logit_s[g][i];
            prob_s[g][i] = (lg > -1e29f) ? expf(lg - newm) : 0.f;
            if (i == 0) { newm_sh[g] = newm; corr_sh[g] = expf(m_sh[g] - newm); }
        }
        __syncthreads();

        // phase 2b: rescale + accumulate AV
        {
            float corr = corr_sh[g2];
            acc0 *= corr; acc1 *= corr; lsum *= corr;
            float psum = 0.f;
#pragma unroll
            for (int i = 0; i < 32; i++) {
                float p = prob_s[g2][i];
                psum += p;
                float2 vv = *(const float2*)&v_s[i][hh * 2];
                acc0 += p * vv.x;
                acc1 += p * vv.y;
            }
            lsum += psum;
            if (hh == 0) m_sh[g2] = newm_sh[g2];
        }
        __syncthreads();
    }

    // write unnormalized partial: acc[4][128], m[4], l[4]
    g_apart[pbase + g2 * 128 + hh * 2]     = acc0;
    g_apart[pbase + g2 * 128 + hh * 2 + 1] = acc1;
    if (hh == 0) {
        g_apart[pbase + 512 + g2] = m_sh[g2];
        g_apart[pbase + 516 + g2] = lsum;
    }
}

// ---------------- Kernel 5: combine attention splits ----------------
__global__ __launch_bounds__(256) void attn_combine()
{
    int b   = blockIdx.x >> 3;
    int kvh = blockIdx.x & 7;
    int t = threadIdx.x;
    int g  = t >> 6;
    int hh = t & 63;

    long base0 = ((long)(b * 8 + kvh) * 4) * 520;
    float m0 = g_apart[base0 + 0 * 520 + 512 + g];
    float m1 = g_apart[base0 + 1 * 520 + 512 + g];
    float m2 = g_apart[base0 + 2 * 520 + 512 + g];
    float m3 = g_apart[base0 + 3 * 520 + 512 + g];
    float M = fmaxf(fmaxf(m0, m1), fmaxf(m2, m3));

    float num0 = 0.f, num1 = 0.f, den = 0.f;
#pragma unroll
    for (int sp = 0; sp < 4; sp++) {
        long bs = base0 + sp * 520;
        float w = expf(g_apart[bs + 512 + g] - M);
        den  += w * g_apart[bs + 516 + g];
        num0 += w * g_apart[bs + g * 128 + hh * 2];
        num1 += w * g_apart[bs + g * 128 + hh * 2 + 1];
    }
    float inv = 1.0f / den;
    int n = kvh * 4 + g;
    *(float2*)&g_obuf[((size_t)b * 32 + n) * 128 + hh * 2] = make_float2(num0 * inv, num1 * inv);
}

// ---------------- Kernel 6: O projection + 384 copy blocks ----------------
__global__ __launch_bounds__(256) void o_copy_kernel(
    const float* __restrict__ o_w,
    const float* __restrict__ cache,
    const int*   __restrict__ slot_mapping,
    float*       __restrict__ out)
{
    __shared__ __align__(16) float as_[64][36];
    __shared__ __align__(16) float ws[32][68];
    __shared__ int s_slots[64];
    __shared__ int s_skip[64];

    int bid = blockIdx.x;
    int grp = bid / 5, lane = bid % 5;          // 2 gemm + 3 copy per group of 5
    if (lane >= 2) {
        copy_rows(NCOPY_QKV + NCOPY_ATTN + grp * 3 + (lane - 2), cache, slot_mapping, out, s_slots, s_skip);
        return;
    }
    int oid = grp * 2 + lane;                   // 0..255
    int nt = oid >> 2;
    int ks = oid & 3;
    int d0 = nt * 64;
    int k0 = ks * 1024;

    int t = threadIdx.x;
    int ty = t >> 4, tx = t & 15;
    float acc[4][4];
#pragma unroll
    for (int i = 0; i < 4; i++)
#pragma unroll
        for (int j = 0; j < 4; j++) acc[i][j] = 0.f;

    for (int kt = 0; kt < 1024; kt += 32) {
#pragma unroll
        for (int r = 0; r < 2; r++) {
            int f = t + 256 * r;
            int row = f >> 3, q4 = f & 7;
            *(float4*)&as_[row][q4 * 4] =
                *(const float4*)(g_obuf + (size_t)row * DMODEL + k0 + kt + q4 * 4);
        }
#pragma unroll
        for (int r = 0; r < 2; r++) {
            int f = t + 256 * r;
            int row = f >> 4, q4 = f & 15;
            *(float4*)&ws[row][q4 * 4] =
                *(const float4*)(o_w + (size_t)(k0 + kt + row) * DMODEL + d0 + q4 * 4);
        }
        __syncthreads();
#pragma unroll
        for (int kk = 0; kk < 32; kk++) {
            float a0 = as_[ty * 4 + 0][kk];
            float a1 = as_[ty * 4 + 1][kk];
            float a2 = as_[ty * 4 + 2][kk];
            float a3 = as_[ty * 4 + 3][kk];
            float4 bv = *(const float4*)&ws[kk][tx * 4];
            acc[0][0] += a0 * bv.x; acc[0][1] += a0 * bv.y; acc[0][2] += a0 * bv.z; acc[0][3] += a0 * bv.w;
            acc[1][0] += a1 * bv.x; acc[1][1] += a1 * bv.y; acc[1][2] += a1 * bv.z; acc[1][3] += a1 * bv.w;
            acc[2][0] += a2 * bv.x; acc[2][1] += a2 * bv.y; acc[2][2] += a2 * bv.z; acc[2][3] += a2 * bv.w;
            acc[3][0] += a3 * bv.x; acc[3][1] += a3 * bv.y; acc[3][2] += a3 * bv.z; acc[3][3] += a3 * bv.w;
        }
        __syncthreads();
    }

    float* dst = g_opart + (size_t)ks * BATCH * DMODEL;
#pragma unroll
    for (int i = 0; i < 4; i++) {
        *(float4*)&dst[(size_t)(ty * 4 + i) * DMODEL + d0 + tx * 4] =
            make_float4(acc[i][0], acc[i][1], acc[i][2], acc[i][3]);
    }
}

// ---------------- Kernel 7: reduce the 4 K-split partials into d_out ----------------
__global__ void o_reduce(float* __restrict__ out_attn)
{
    int i = blockIdx.x * 256 + threadIdx.x;
    float s = g_opart[i]
            + g_opart[i + BATCH * DMODEL]
            + g_opart[i + 2 * BATCH * DMODEL]
            + g_opart[i + 3 * BATCH * DMODEL];
    out_attn[i] = s;
}

// ---------------- launch ----------------
extern "C" void kernel_launch(void* const* d_in, const int* in_sizes, int n_in,
                              void* d_out, int out_size)
{
    const float* x            = (const float*)d_in[0];
    const int*   slot_mapping = (const int*)d_in[2];
    const int*   block_tables = (const int*)d_in[3];
    const int*   context_lens = (const int*)d_in[4];
    const float* cache        = (const float*)d_in[5];
    const float* q_w          = (const float*)d_in[6];
    const float* kv_w         = (const float*)d_in[7];
    const float* o_w          = (const float*)d_in[8];
    float* out = (float*)d_out;

    // 1) QKV projection (384 blocks) + 50% of cache copy (1024 blocks) fused
    qkv_copy_kernel<<<NMAT * KSPLIT + NCOPY_QKV, 256>>>(x, q_w, kv_w, cache, slot_mapping, out);

    // 2) K-split reduce + RoPE
    reduce_rope<<<(NMAT * BATCH * 64 + 255) / 256, 256>>>(context_lens);

    // 3) write the new k/v rows (copy blocks skip these slots)
    cache_scatter<<<BATCH, 256>>>(slot_mapping, out);

    // 4) split-KV attention (2048 blocks) + 31% of copy (640 blocks) fused
    attn_copy_kernel<<<(2048 / 16) * 21, 256>>>(cache, block_tables, context_lens, slot_mapping, out);

    // 5) combine split partials
    attn_combine<<<BATCH * KVHEADS, 256>>>();

    // 6) O projection (256 blocks) + 19% of copy (384 blocks) fused
    o_copy_kernel<<<(256 / 2) * 5, 256>>>(o_w, cache, slot_mapping, out);

    // 7) final K-split reduce into attention output
    o_reduce<<<(BATCH * DMODEL) / 256, 256>>>(out + ATTN_OUT_OFF);
}

// round 16
// speedup vs baseline: 1.5957x; 1.0035x over previous
#include <cuda_runtime.h>
#include <math.h>

#define BATCH 64
#define DMODEL 4096
#define NHEADS 32
#define KVHEADS 8
#define HDIM 128
#define NMAT 48
#define KSPLIT 8
#define KCHUNK (DMODEL / KSPLIT)   // 512
#define CACHE_HALF 67108864L       // 65536 * 8 * 128
#define ATTN_OUT_OFF 134217728L    // 2 * CACHE_HALF
#define ASPLIT 4                   // attention KV splits (256 positions each)
#define TOTAL_ROWS 131072L         // 2 * 65536 cache rows of 1024 floats
#define ROWS_PER_COPY 64
#define NCOPY 2048                 // total copy blocks
#define NCOPY_QKV 1024
#define NCOPY_ATTN 640
#define NCOPY_O 384

// ---------------- scratch (allocation-free, __device__ globals) ----------------
__device__ __align__(16) float g_qkv_part[NMAT * KSPLIT * BATCH * HDIM]; // 12.6 MB
__device__ __align__(16) float g_qbuf[BATCH * NHEADS * HDIM];
__device__ __align__(16) float g_kbuf[BATCH * KVHEADS * HDIM];
__device__ __align__(16) float g_vbuf[BATCH * KVHEADS * HDIM];
__device__ __align__(16) float g_obuf[BATCH * NHEADS * HDIM];
__device__ __align__(16) float g_opart[4 * BATCH * DMODEL];              // 4 MB
__device__ __align__(16) float g_apart[BATCH * KVHEADS * ASPLIT * 520]; // 4.3 MB

// ---------------- cp.async helpers ----------------
__device__ __forceinline__ void cp_async16(void* dst, const void* src) {
    unsigned d = (unsigned)__cvta_generic_to_shared(dst);
    asm volatile("cp.async.cg.shared.global [%0], [%1], 16;\n" :: "r"(d), "l"(src));
}
__device__ __forceinline__ void cp_commit_wait_all() {
    asm volatile("cp.async.commit_group;\ncp.async.wait_group 0;\n" ::: "memory");
}

// ---------------- shared copy path: copy 64 cache rows, skipping scatter slots ----------------
__device__ __forceinline__ void copy_rows(int cid,
                                          const float* __restrict__ cache,
                                          const int* __restrict__ slot_mapping,
                                          float* __restrict__ out,
                                          int* s_slots, int* s_skip)
{
    int t = threadIdx.x;
    if (t < 64) s_slots[t] = slot_mapping[t];
    __syncthreads();
    long r0 = (long)cid << 6;                  // 64 rows per block, same cache half
    if (t < 64) {
        int slot = (int)((r0 + t) & 65535L);
        int sk = 0;
#pragma unroll 8
        for (int i = 0; i < 64; i++) sk |= (s_slots[i] == slot);
        s_skip[t] = sk;
    }
    __syncthreads();
    const float4* src = (const float4*)cache + (r0 << 8) + t;  // 256 float4 per row
    float4*       dst = (float4*)out         + (r0 << 8) + t;
#pragma unroll 8
    for (int it = 0; it < 64; it++) {
        if (!s_skip[it]) dst[it * 256] = src[it * 256];
    }
}

// ---------------- Kernel 1: QKV projection + 1024 copy blocks ----------------
__global__ __launch_bounds__(256) void qkv_copy_kernel(
    const float* __restrict__ x,
    const float* __restrict__ q_w,
    const float* __restrict__ kv_w,
    const float* __restrict__ cache,
    const int*   __restrict__ slot_mapping,
    float*       __restrict__ out)
{
    __shared__ __align__(16) float xs[64][36];
    __shared__ __align__(16) float ws[32][132];
    __shared__ int s_slots[64];
    __shared__ int s_skip[64];

    int bid = blockIdx.x;
    if (bid >= NMAT * KSPLIT) {                 // copy block
        copy_rows(bid - NMAT * KSPLIT, cache, slot_mapping, out, s_slots, s_skip);
        return;
    }
    int mat = bid >> 3;
    int ks  = bid & 7;
    const float* W = (mat < 32) ? (q_w  + (size_t)mat * DMODEL * HDIM)
                                : (kv_w + (size_t)(mat - 32) * DMODEL * HDIM);
    int d0 = ks * KCHUNK;

    int t  = threadIdx.x;
    int ty = t >> 4;
    int tx = t & 15;

    float acc[4][8];
#pragma unroll
    for (int i = 0; i < 4; i++)
#pragma unroll
        for (int j = 0; j < 8; j++) acc[i][j] = 0.f;

    for (int dt = 0; dt < KCHUNK; dt += 32) {
#pragma unroll
        for (int r = 0; r < 2; r++) {
            int f = t + 256 * r;
            int row = f >> 3, q4 = f & 7;
            *(float4*)&xs[row][q4 * 4] =
                *(const float4*)(x + (size_t)row * DMODEL + d0 + dt + q4 * 4);
        }
#pragma unroll
        for (int r = 0; r < 4; r++) {
            int f = t + 256 * r;
            int row = f >> 5, q4 = f & 31;
            *(float4*)&ws[row][q4 * 4] =
                *(const float4*)(W + (size_t)(d0 + dt + row) * HDIM + q4 * 4);
        }
        __syncthreads();
#pragma unroll
        for (int kk = 0; kk < 32; kk++) {
            float a0 = xs[ty * 4 + 0][kk];
            float a1 = xs[ty * 4 + 1][kk];
            float a2 = xs[ty * 4 + 2][kk];
            float a3 = xs[ty * 4 + 3][kk];
            float4 b0 = *(const float4*)&ws[kk][tx * 8];
            float4 b1 = *(const float4*)&ws[kk][tx * 8 + 4];
            acc[0][0] += a0 * b0.x; acc[0][1] += a0 * b0.y; acc[0][2] += a0 * b0.z; acc[0][3] += a0 * b0.w;
            acc[0][4] += a0 * b1.x; acc[0][5] += a0 * b1.y; acc[0][6] += a0 * b1.z; acc[0][7] += a0 * b1.w;
            acc[1][0] += a1 * b0.x; acc[1][1] += a1 * b0.y; acc[1][2] += a1 * b0.z; acc[1][3] += a1 * b0.w;
            acc[1][4] += a1 * b1.x; acc[1][5] += a1 * b1.y; acc[1][6] += a1 * b1.z; acc[1][7] += a1 * b1.w;
            acc[2][0] += a2 * b0.x; acc[2][1] += a2 * b0.y; acc[2][2] += a2 * b0.z; acc[2][3] += a2 * b0.w;
            acc[2][4] += a2 * b1.x; acc[2][5] += a2 * b1.y; acc[2][6] += a2 * b1.z; acc[2][7] += a2 * b1.w;
            acc[3][0] += a3 * b0.x; acc[3][1] += a3 * b0.y; acc[3][2] += a3 * b0.z; acc[3][3] += a3 * b0.w;
            acc[3][4] += a3 * b1.x; acc[3][5] += a3 * b1.y; acc[3][6] += a3 * b1.z; acc[3][7] += a3 * b1.w;
        }
        __syncthreads();
    }

    float* dst = g_qkv_part + ((size_t)(mat * 8 + ks) * 64) * 128;
#pragma unroll
    for (int i = 0; i < 4; i++) {
        int row = ty * 4 + i;
        *(float4*)&dst[row * 128 + tx * 8]     = make_float4(acc[i][0], acc[i][1], acc[i][2], acc[i][3]);
        *(float4*)&dst[row * 128 + tx * 8 + 4] = make_float4(acc[i][4], acc[i][5], acc[i][6], acc[i][7]);
    }
}

// ---------------- Kernel 2: reduce K-split partials + RoPE ----------------
__global__ __launch_bounds__(256) void reduce_rope(const int* __restrict__ context_lens)
{
    int tid = blockIdx.x * 256 + threadIdx.x;
    if (tid >= NMAT * BATCH * 64) return;
    int mat = tid >> 12;
    int rem = tid & 4095;
    int b = rem >> 6;
    int j = rem & 63;

    float v1 = 0.f, v2 = 0.f;
    size_t off = ((size_t)(mat * 8) * 64 + b) * 128;
#pragma unroll
    for (int ks = 0; ks < 8; ks++) {
        v1 += g_qkv_part[off + j];
        v2 += g_qkv_part[off + 64 + j];
        off += 64 * 128;
    }

    float o1 = v1, o2 = v2;
    if (mat < 40) {
        float pos = (float)(context_lens[b] - 1);
        float ts = powf(10000.0f, (float)j * (1.0f / 64.0f));
        float ang = pos / ts;
        float s = sinf(ang), c = cosf(ang);
        o1 = v1 * c - v2 * s;
        o2 = v2 * c + v1 * s;
    }

    if (mat < 32) {
        float* d = g_qbuf + ((size_t)b * 32 + mat) * 128;
        d[j] = o1; d[j + 64] = o2;
    } else if (mat < 40) {
        float* d = g_kbuf + ((size_t)b * 8 + (mat - 32)) * 128;
        d[j] = o1; d[j + 64] = o2;
    } else {
        float* d = g_vbuf + ((size_t)b * 8 + (mat - 40)) * 128;
        d[j] = o1; d[j + 64] = o2;
    }
}

// ---------------- Kernel 3: write the new k/v rows (copy blocks skipped these) ----------------
__global__ void cache_scatter(const int* __restrict__ slot_mapping, float* __restrict__ out)
{
    int b = blockIdx.x;
    int slot = slot_mapping[b];
    int t = threadIdx.x;
    const float4* ksrc = (const float4*)(g_kbuf + (size_t)b * 1024);
    const float4* vsrc = (const float4*)(g_vbuf + (size_t)b * 1024);
    float4* dk = (float4*)(out + (size_t)slot * 1024);
    float4* dv = (float4*)(out + CACHE_HALF + (size_t)slot * 1024);
    dk[t] = ksrc[t];
    dv[t] = vsrc[t];
}

// ---------------- Kernel 4: split-KV attention + 640 copy blocks ----------------
// attn blocks: aid = b*32 + kvh*4 + sp; each handles positions [sp*256, sp*256+256)
__global__ __launch_bounds__(256) void attn_copy_kernel(
    const float* __restrict__ cache,
    const int*   __restrict__ block_tables,
    const int*   __restrict__ context_lens,
    const int*   __restrict__ slot_mapping,
    float*       __restrict__ out)
{
    __shared__ __align__(16) float q_s[4][132];
    __shared__ __align__(16) float k_s[32][132];
    __shared__ __align__(16) float v_s[32][132];
    __shared__ float logit_s[4][32];
    __shared__ float prob_s[4][32];
    __shared__ float m_sh[4], newm_sh[4], corr_sh[4];
    __shared__ int   bt_s[16];
    __shared__ int   s_slots[64];
    __shared__ int   s_skip[64];

    int bid = blockIdx.x;
    int grp = bid / 21, lane = bid % 21;       // 16 attn + 5 copy per group of 21
    if (lane >= 16) {
        copy_rows(NCOPY_QKV + grp * 5 + (lane - 16), cache, slot_mapping, out, s_slots, s_skip);
        return;
    }
    int aid = grp * 16 + lane;
    int b   = aid >> 5;
    int kvh = (aid >> 2) & 7;
    int sp  = aid & 3;
    int t = threadIdx.x;

    int ctx = context_lens[b];
    int start = sp << 8;
    long pbase = (long)aid * 520;
    if (start >= ctx) {
        if (t < 4) {
            g_apart[pbase + 512 + t] = -INFINITY;
            g_apart[pbase + 516 + t] = 0.f;
        }
        return;
    }
    int end = min(ctx, start + 256);

    if (t < 16) bt_s[t] = block_tables[b * 64 + sp * 16 + t];

    const float sm_scale = 0.08838834764831845f;
#pragma unroll
    for (int r = 0; r < 2; r++) {
        int f = t + 256 * r;
        int g = f >> 7, h = f & 127;
        q_s[g][h] = g_qbuf[((size_t)b * 32 + kvh * 4 + g) * 128 + h] * sm_scale;
    }
    if (t < 4) m_sh[t] = -INFINITY;

    float acc0 = 0.f, acc1 = 0.f, lsum = 0.f;
    int g2 = t >> 6;
    int hh = t & 63;
    __syncthreads();

    const float* kc = cache;
    const float* vc = cache + CACHE_HALF;

    int nchunk = (end - start + 31) >> 5;
    for (int c = 0; c < nchunk; c++) {
        int p0 = start + (c << 5);
        // async load of K/V chunk (32 positions x 128 floats each)
#pragma unroll
        for (int r = 0; r < 4; r++) {
            int f = t + 256 * r;
            int row = f >> 5;
            int q4  = f & 31;
            int pos = p0 + row;
            int posc = min(pos, ctx - 1);
            const float* ks;
            const float* vs;
            if (posc == ctx - 1) {
                ks = g_kbuf + ((size_t)b * 8 + kvh) * 128 + q4 * 4;
                vs = g_vbuf + ((size_t)b * 8 + kvh) * 128 + q4 * 4;
            } else {
                int slot = bt_s[(posc >> 4) & 15] * 16 + (posc & 15);
                size_t off = (size_t)slot * 1024 + kvh * 128 + q4 * 4;
                ks = kc + off;
                vs = vc + off;
            }
            cp_async16(&k_s[row][q4 * 4], ks);
            cp_async16(&v_s[row][q4 * 4], vs);
        }
        cp_commit_wait_all();
        __syncthreads();

        // phase 1: logits
        if (t < 128) {
            int g = t & 3, i = t >> 2;
            int pos = p0 + i;
            float lg = -1e30f;
            if (pos < ctx) {
                float sum = 0.f;
#pragma unroll
                for (int j = 0; j < 32; j++) {
                    float4 qv = *(const float4*)&q_s[g][j * 4];
                    float4 kv = *(const float4*)&k_s[i][j * 4];
                    sum += qv.x * kv.x + qv.y * kv.y + qv.z * kv.z + qv.w * kv.w;
                }
                lg = sum;
            }
            logit_s[g][i] = lg;
        }
        __syncthreads();

        // phase 2a: chunk max + probs
        if (t < 128) {
            int g = t & 3, i = t >> 2;
            float cmax = -INFINITY;
#pragma unroll
            for (int ii = 0; ii < 32; ii++) cmax = fmaxf(cmax, logit_s[g][ii]);
            float newm = fmaxf(m_sh[g], cmax);
            float lg = logit_s[g][i];
            prob_s[g][i] = (lg > -1e29f) ? expf(lg - newm) : 0.f;
            if (i == 0) { newm_sh[g] = newm; corr_sh[g] = expf(m_sh[g] - newm); }
        }
        __syncthreads();

        // phase 2b: rescale + accumulate AV
        {
            float corr = corr_sh[g2];
            acc0 *= corr; acc1 *= corr; lsum *= corr;
            float psum = 0.f;
#pragma unroll
            for (int i = 0; i < 32; i++) {
                float p = prob_s[g2][i];
                psum += p;
                float2 vv = *(const float2*)&v_s[i][hh * 2];
                acc0 += p * vv.x;
                acc1 += p * vv.y;
            }
            lsum += psum;
            if (hh == 0) m_sh[g2] = newm_sh[g2];
        }
        __syncthreads();
    }

    // write unnormalized partial: acc[4][128], m[4], l[4]
    g_apart[pbase + g2 * 128 + hh * 2]     = acc0;
    g_apart[pbase + g2 * 128 + hh * 2 + 1] = acc1;
    if (hh == 0) {
        g_apart[pbase + 512 + g2] = m_sh[g2];
        g_apart[pbase + 516 + g2] = lsum;
    }
}

// ---------------- Kernel 5: combine attention splits ----------------
__global__ __launch_bounds__(256) void attn_combine()
{
    int b   = blockIdx.x >> 3;
    int kvh = blockIdx.x & 7;
    int t = threadIdx.x;
    int g  = t >> 6;
    int hh = t & 63;

    long base0 = ((long)(b * 8 + kvh) * 4) * 520;
    float m0 = g_apart[base0 + 0 * 520 + 512 + g];
    float m1 = g_apart[base0 + 1 * 520 + 512 + g];
    float m2 = g_apart[base0 + 2 * 520 + 512 + g];
    float m3 = g_apart[base0 + 3 * 520 + 512 + g];
    float M = fmaxf(fmaxf(m0, m1), fmaxf(m2, m3));

    float num0 = 0.f, num1 = 0.f, den = 0.f;
#pragma unroll
    for (int sp = 0; sp < 4; sp++) {
        long bs = base0 + sp * 520;
        float w = expf(g_apart[bs + 512 + g] - M);
        den  += w * g_apart[bs + 516 + g];
        num0 += w * g_apart[bs + g * 128 + hh * 2];
        num1 += w * g_apart[bs + g * 128 + hh * 2 + 1];
    }
    float inv = 1.0f / den;
    int n = kvh * 4 + g;
    *(float2*)&g_obuf[((size_t)b * 32 + n) * 128 + hh * 2] = make_float2(num0 * inv, num1 * inv);
}

// ---------------- Kernel 6: O projection + 384 copy blocks ----------------
__global__ __launch_bounds__(256) void o_copy_kernel(
    const float* __restrict__ o_w,
    const float* __restrict__ cache,
    const int*   __restrict__ slot_mapping,
    float*       __restrict__ out)
{
    __shared__ __align__(16) float as_[64][36];
    __shared__ __align__(16) float ws[32][68];
    __shared__ int s_slots[64];
    __shared__ int s_skip[64];

    int bid = blockIdx.x;
    int grp = bid / 5, lane = bid % 5;          // 2 gemm + 3 copy per group of 5
    if (lane >= 2) {
        copy_rows(NCOPY_QKV + NCOPY_ATTN + grp * 3 + (lane - 2), cache, slot_mapping, out, s_slots, s_skip);
        return;
    }
    int oid = grp * 2 + lane;                   // 0..255
    int nt = oid >> 2;
    int ks = oid & 3;
    int d0 = nt * 64;
    int k0 = ks * 1024;

    int t = threadIdx.x;
    int ty = t >> 4, tx = t & 15;
    float acc[4][4];
#pragma unroll
    for (int i = 0; i < 4; i++)
#pragma unroll
        for (int j = 0; j < 4; j++) acc[i][j] = 0.f;

    for (int kt = 0; kt < 1024; kt += 32) {
#pragma unroll
        for (int r = 0; r < 2; r++) {
            int f = t + 256 * r;
            int row = f >> 3, q4 = f & 7;
            *(float4*)&as_[row][q4 * 4] =
                *(const float4*)(g_obuf + (size_t)row * DMODEL + k0 + kt + q4 * 4);
        }
#pragma unroll
        for (int r = 0; r < 2; r++) {
            int f = t + 256 * r;
            int row = f >> 4, q4 = f & 15;
            *(float4*)&ws[row][q4 * 4] =
                *(const float4*)(o_w + (size_t)(k0 + kt + row) * DMODEL + d0 + q4 * 4);
        }
        __syncthreads();
#pragma unroll
        for (int kk = 0; kk < 32; kk++) {
            float a0 = as_[ty * 4 + 0][kk];
            float a1 = as_[ty * 4 + 1][kk];
            float a2 = as_[ty * 4 + 2][kk];
            float a3 = as_[ty * 4 + 3][kk];
            float4 bv = *(const float4*)&ws[kk][tx * 4];
            acc[0][0] += a0 * bv.x; acc[0][1] += a0 * bv.y; acc[0][2] += a0 * bv.z; acc[0][3] += a0 * bv.w;
            acc[1][0] += a1 * bv.x; acc[1][1] += a1 * bv.y; acc[1][2] += a1 * bv.z; acc[1][3] += a1 * bv.w;
            acc[2][0] += a2 * bv.x; acc[2][1] += a2 * bv.y; acc[2][2] += a2 * bv.z; acc[2][3] += a2 * bv.w;
            acc[3][0] += a3 * bv.x; acc[3][1] += a3 * bv.y; acc[3][2] += a3 * bv.z; acc[3][3] += a3 * bv.w;
        }
        __syncthreads();
    }

    float* dst = g_opart + (size_t)ks * BATCH * DMODEL;
#pragma unroll
    for (int i = 0; i < 4; i++) {
        *(float4*)&dst[(size_t)(ty * 4 + i) * DMODEL + d0 + tx * 4] =
            make_float4(acc[i][0], acc[i][1], acc[i][2], acc[i][3]);
    }
}

// ---------------- Kernel 7: reduce the 4 K-split partials into d_out ----------------
__global__ void o_reduce(float* __restrict__ out_attn)
{
    int i = blockIdx.x * 256 + threadIdx.x;
    float s = g_opart[i]
            + g_opart[i + BATCH * DMODEL]
            + g_opart[i + 2 * BATCH * DMODEL]
            + g_opart[i + 3 * BATCH * DMODEL];
    out_attn[i] = s;
}

// ---------------- launch ----------------
extern "C" void kernel_launch(void* const* d_in, const int* in_sizes, int n_in,
                              void* d_out, int out_size)
{
    const float* x            = (const float*)d_in[0];
    const int*   slot_mapping = (const int*)d_in[2];
    const int*   block_tables = (const int*)d_in[3];
    const int*   context_lens = (const int*)d_in[4];
    const float* cache        = (const float*)d_in[5];
    const float* q_w          = (const float*)d_in[6];
    const float* kv_w         = (const float*)d_in[7];
    const float* o_w          = (const float*)d_in[8];
    float* out = (float*)d_out;

    // 1) QKV projection (384 blocks) + 50% of cache copy (1024 blocks) fused
    qkv_copy_kernel<<<NMAT * KSPLIT + NCOPY_QKV, 256>>>(x, q_w, kv_w, cache, slot_mapping, out);

    // 2) K-split reduce + RoPE
    reduce_rope<<<(NMAT * BATCH * 64 + 255) / 256, 256>>>(context_lens);

    // 3) write the new k/v rows (copy blocks skip these slots)
    cache_scatter<<<BATCH, 256>>>(slot_mapping, out);

    // 4) split-KV attention (2048 blocks) + 31% of copy (640 blocks) fused
    attn_copy_kernel<<<(2048 / 16) * 21, 256>>>(cache, block_tables, context_lens, slot_mapping, out);

    // 5) combine split partials
    attn_combine<<<BATCH * KVHEADS, 256>>>();

    // 6) O projection (256 blocks) + 19% of copy (384 blocks) fused
    o_copy_kernel<<<(256 / 2) * 5, 256>>>(o_w, cache, slot_mapping, out);

    // 7) final K-split reduce into attention output
    o_reduce<<<(BATCH * DMODEL) / 256, 256>>>(out + ATTN_OUT_OFF);
}